// round 1
// baseline (speedup 1.0000x reference)
#include <cuda_runtime.h>
#include <cuda_bf16.h>

// SEIR RNN: 65536 independent 4-state ODE trajectories, 200 explicit-Euler
// steps, every step's state written out.  Pure HBM-store-bound (210 MB out).
//
// Mapping: 1 thread = 1 trajectory, state lives in registers.  Steps are
// processed in chunks of 8; each chunk is staged in shared memory (padded
// for conflict-free 128-bit access) and then written to global memory fully
// coalesced (8 lanes cover one trajectory's 8 consecutive step-float4s =
// one 128B line).

#define BATCH   65536
#define STEPS   200
#define CHUNK   8
#define NCHUNK  (STEPS / CHUNK)   // 25
#define TPB     128

__global__ __launch_bounds__(TPB, 8)
void seir_kernel(const float4* __restrict__ init,
                 const float*  __restrict__ w,
                 float4*       __restrict__ out)
{
    // +1 float4 pad per row: thread stride = 9*16 = 144 B, so the 8 lanes of
    // each 128-bit access phase hit distinct 16B sub-banks (0,16,...,112 mod 128).
    __shared__ float4 buf[TPB][CHUNK + 1];

    const int tid = threadIdx.x;
    const int b0  = blockIdx.x * TPB;
    const int b   = b0 + tid;

    const float A = w[4];
    const float B = w[5];
    const float C = w[6];
    const float inv_npop = 1.0f / 100000.0f;
    const float H     =  0.5f;
    const float CLAMP =  100000.0f;

    float4 x = init[b];
    float s = x.x, e = x.y, i = x.z, r = x.w;

    for (int c = 0; c < NCHUNK; ++c) {
        // ---- compute 8 steps, stage in shared ----
        #pragma unroll
        for (int t = 0; t < CHUNK; ++t) {
            float infl = B * s * (e + i) * inv_npop;
            float d0 = -infl;
            float d1 = infl - A * e;
            float d2 = A * e - C * i;
            float d3 = C * i;
            d0 = fminf(fmaxf(d0, -CLAMP), CLAMP);
            d1 = fminf(fmaxf(d1, -CLAMP), CLAMP);
            d2 = fminf(fmaxf(d2, -CLAMP), CLAMP);
            d3 = fminf(fmaxf(d3, -CLAMP), CLAMP);
            s += H * d0;
            e += H * d1;
            i += H * d2;
            r += H * d3;
            buf[tid][t] = make_float4(s, e, i, r);
        }
        __syncthreads();

        // ---- coalesced drain: idx enumerates (trajectory-row, step) so that
        //      8 consecutive lanes write 8 consecutive float4s of one row ----
        const int tbase = c * CHUNK;
        #pragma unroll
        for (int k = 0; k < CHUNK; ++k) {
            int idx = k * TPB + tid;          // 0 .. TPB*CHUNK-1
            int bl  = idx >> 3;               // local trajectory
            int t   = idx & 7;                // step within chunk
            out[(size_t)(b0 + bl) * STEPS + (tbase + t)] = buf[bl][t];
        }
        __syncthreads();
    }
}

extern "C" void kernel_launch(void* const* d_in, const int* in_sizes, int n_in,
                              void* d_out, int out_size)
{
    const float4* init = (const float4*)d_in[0];   // (65536,1,4) f32
    const float*  wts  = (const float*)d_in[1];    // (7,) f32
    float4*       out  = (float4*)d_out;           // (65536,200,1,4) f32

    seir_kernel<<<BATCH / TPB, TPB>>>(init, wts, out);
}